// round 12
// baseline (speedup 1.0000x reference)
#include <cuda_runtime.h>
#include <cuda_bf16.h>
#include <cuda_fp16.h>
#include <stdint.h>

// ---------------------------------------------------------------------------
// out[b,s,p] = sum_l softmax_l( sum_r q[b,s,r]*k[b,l,r]*Wc[p,r] ) * v[b,l,p]
// scores = K_b @ (diag(q_s) Wc^T), single-pass fp16 mma.sync (score err RMS
// ~2e-4 << 1e-3). bc cancels; max subtraction dropped (scores O(1)).
// CTA = (b, s, ph, lh): M=128, N=128; grid 2048, block 256 (8 warps 2x4,
// warp tile 64x32); 2 CTAs/SM. 4 chunks of 64 r, SW128 128B rows,
// double-buffered cp.async A; B = fp16(q*Wc) built in-kernel, staged in two
// 32-r halves interleaved with the MMA ksteps.
// ---------------------------------------------------------------------------

__device__ float g_WqkvT[256 * 768];           // [h][j]
__device__ float g_q[2 * 256 * 256];
__device__ float g_v[2 * 256 * 256];
// K fp16, pre-swizzled SW128 tiles: [b][chunk 0..3][32768 bytes]
// (32KB tile = 256 l rows x 128B; row l holds 64 r values)
__device__ char g_ka[2 * 4 * 32768];
// partial softmax sums: [lh][ ((b*256+s)*256 + ph*128 + p) ]
__device__ float g_pden[2 * 131072];
__device__ float g_pnum[2 * 131072];

// ------------------------------ helpers ------------------------------------
__device__ __forceinline__ uint32_t smem_u32(const void* p) {
    uint32_t a;
    asm("{ .reg .u64 t; cvta.to.shared.u64 t, %1; cvt.u32.u64 %0, t; }"
        : "=r"(a) : "l"(p));
    return a;
}
__device__ __forceinline__ uint32_t swz(uint32_t off) {   // SW128
    return off ^ ((off >> 3) & 0x70);
}
__device__ __forceinline__ void ldsm4(uint32_t* r, uint32_t addr) {
    asm volatile("ldmatrix.sync.aligned.m8n8.x4.shared.b16 {%0,%1,%2,%3}, [%4];"
        : "=r"(r[0]), "=r"(r[1]), "=r"(r[2]), "=r"(r[3]) : "r"(addr));
}
__device__ __forceinline__ void mma16816h(float* d, const uint32_t* a,
                                          uint32_t b0, uint32_t b1) {
    asm volatile(
        "mma.sync.aligned.m16n8k16.row.col.f32.f16.f16.f32 "
        "{%0,%1,%2,%3}, {%4,%5,%6,%7}, {%8,%9}, {%0,%1,%2,%3};"
        : "+f"(d[0]), "+f"(d[1]), "+f"(d[2]), "+f"(d[3])
        : "r"(a[0]), "r"(a[1]), "r"(a[2]), "r"(a[3]), "r"(b0), "r"(b1));
}
__device__ __forceinline__ uint32_t packh2(float v0, float v1) {
    uint32_t h;
    asm("cvt.rn.f16x2.f32 %0, %1, %2;" : "=r"(h) : "f"(v1), "f"(v0));
    return h;
}
__device__ __forceinline__ void cp16(uint32_t dst, const void* src) {
    asm volatile("cp.async.cg.shared.global [%0], [%1], 16;"
                 :: "r"(dst), "l"(src));
}
#define CP_COMMIT() asm volatile("cp.async.commit_group;" ::: "memory")
#define CP_WAIT0()  asm volatile("cp.async.wait_group 0;" ::: "memory")

// ---------------------------------------------------------------------------
// Prep kernels
// ---------------------------------------------------------------------------
__global__ void transpose_kernel(const float* __restrict__ in, float* __restrict__ out,
                                 int rows, int cols) {
    __shared__ float tile[32][33];
    int ctiles = cols >> 5;
    int bx = blockIdx.x % ctiles, by = blockIdx.x / ctiles;
    int c0 = bx << 5, r0 = by << 5;
    int tx = threadIdx.x & 31, ty = threadIdx.x >> 5;
#pragma unroll
    for (int i = ty; i < 32; i += 8)
        tile[i][tx] = in[(r0 + i) * cols + c0 + tx];
    __syncthreads();
#pragma unroll
    for (int i = ty; i < 32; i += 8)
        out[(c0 + i) * rows + r0 + tx] = tile[tx][i];
}

// QKV projection, 2D grid: blockIdx.x = j-block (0..2: q/k/v), blockIdx.y =
// row-block (8 rows). block = 256 threads (one j each). K section writes fp16
// directly into the pre-swizzled SW128 g_ka tiles.
__global__ void qkv_kernel(const float* __restrict__ hidden,
                           const float* __restrict__ bqkv) {
    __shared__ float hs[8][256];
    int t = threadIdx.x;
    int jb = blockIdx.x;
    int row0 = blockIdx.y << 3;
    for (int i = t; i < 2048; i += 256)
        hs[i >> 8][i & 255] = hidden[(row0 << 8) + i];
    __syncthreads();

    int j = jb * 256 + t;
    float a[8];
#pragma unroll
    for (int i = 0; i < 8; i++) a[i] = 0.f;
    const float* w = g_WqkvT + j;
#pragma unroll 8
    for (int h = 0; h < 256; h++) {
        float wv = w[h * 768];
#pragma unroll
        for (int i = 0; i < 8; i++) a[i] = fmaf(hs[i][h], wv, a[i]);
    }
    float bias = bqkv[j];
#pragma unroll
    for (int i = 0; i < 8; i++) a[i] += bias;

    if (jb == 1) {
        // K: fp16 into pre-swizzled tiles. r = t.
        int c = t >> 6, rl = t & 63;
#pragma unroll
        for (int i = 0; i < 8; i++) {
            int row = row0 + i;
            int b = row >> 8, l = row & 255;
            uint32_t off = swz((uint32_t)(l * 128 + rl * 2));
            char* base = g_ka + ((b * 4 + c) << 15);
            *(unsigned short*)(base + off) =
                __half_as_ushort(__float2half_rn(a[i]));
        }
    } else {
        float* dst = (jb == 0) ? g_q : g_v;
#pragma unroll
        for (int i = 0; i < 8; i++)
            dst[(row0 + i) * 256 + t] = a[i];
    }
}

// ---------------------------------------------------------------------------
// Fused attention kernel. CTA = (b, s, ph, lh). grid = 2048, block = 256.
// 8 warps as 2(M) x 4(N), warp tile 64x32. 4 chunks of 64 r, double buffered.
// ---------------------------------------------------------------------------
#define A_BUF(buf) ((uint32_t)(buf) * 16384u)
#define B_BUF(buf) (32768u + (uint32_t)(buf) * 16384u)
#define OFF_QS  65536
#define OFF_DEN 66560
#define OFF_NUM 67584
#define SMEM_BYTES 68608

__global__ void __launch_bounds__(256, 2)
attn_mma_kernel(const float* __restrict__ Wc) {
    extern __shared__ char smem[];
    uint32_t sb = smem_u32(smem);
    int t = threadIdx.x;
    int lane = t & 31, w = t >> 5;
    int wm = w & 1, wn = w >> 1;           // 2(M) x 4(N) warps; tile 64 x 32
    int lh = blockIdx.x & 1;
    int ph = (blockIdx.x >> 1) & 1;
    int s = (blockIdx.x >> 2) & 255;
    int b = blockIdx.x >> 10;

    float* qs = (float*)(smem + OFF_QS);

    float acc[4][4][4];
#pragma unroll
    for (int mt = 0; mt < 4; mt++)
#pragma unroll
        for (int nt = 0; nt < 4; nt++)
#pragma unroll
            for (int i = 0; i < 4; i++) acc[mt][nt][i] = 0.f;

    // ldmatrix lane byte offset for 128B rows; hoisted SW128 swizzle (XOR).
    int g = lane >> 3;
    uint32_t laneterm = (uint32_t)((((g & 1) << 3) + (lane & 7)) * 128 + ((g >> 1) << 4));
    uint32_t swzlt = swz(laneterm);
    uint32_t arowoff = (uint32_t)(wm * 64) * 128;   // wm<<13
    uint32_t browoff = (uint32_t)(wn * 32) * 128;   // wn<<12

    // B staging: thread -> (p row bp, 32-r half bq of the 64-r chunk)
    int bp = t >> 1, bq = t & 1;
    const float* wcrow = Wc + ((ph << 7) + bp) * 256;
    // A source: this CTA's l-half of each 32KB chunk tile
    const char* kabase = g_ka + ((b * 4) << 15) + lh * 16384;  // + c*32768

    // ---- prologue: cp.async A chunk0, q load, B chunk0 ----
#pragma unroll
    for (int i = 0; i < 4; i++) {
        uint32_t o = (uint32_t)(t * 64 + i * 16);
        cp16(sb + A_BUF(0) + o, kabase + o);
    }
    CP_COMMIT();
    qs[t] = g_q[((b << 8) + s) * 256 + t];
    __syncthreads();
    {
        const float4* wp = (const float4*)(wcrow + bq * 32);
        const float* qq = qs + bq * 32;
#pragma unroll
        for (int hf = 0; hf < 2; hf++) {
#pragma unroll
            for (int k = 0; k < 2; k++) {
                float4 w0 = wp[hf * 4 + k * 2], w1 = wp[hf * 4 + k * 2 + 1];
                const float* q8 = qq + hf * 16 + k * 8;
                uint4 hv;
                hv.x = packh2(w0.x * q8[0], w0.y * q8[1]);
                hv.y = packh2(w0.z * q8[2], w0.w * q8[3]);
                hv.z = packh2(w1.x * q8[4], w1.y * q8[5]);
                hv.w = packh2(w1.z * q8[6], w1.w * q8[7]);
                uint32_t o = swz((uint32_t)(bp * 128 + bq * 64 + (hf * 2 + k) * 16));
                *(uint4*)(smem + B_BUF(0) + o) = hv;
            }
        }
    }

    // ---- main loop over 4 chunks of 64 r ----
    for (int c = 0; c < 4; c++) {
        int buf = c & 1;
        CP_WAIT0();
        __syncthreads();

        uint32_t Ab = sb + A_BUF(buf) + arowoff;
        uint32_t Bb = sb + B_BUF(buf) + browoff;

        float4 bw0, bw1, bw2, bw3;
        const float4* wp = (const float4*)(wcrow + (c + 1) * 64 + bq * 32);
        const float* qq = qs + (c + 1) * 64 + bq * 32;
        if (c < 3) {
            // cp.async A chunk c+1 into other buffer
#pragma unroll
            for (int i = 0; i < 4; i++) {
                uint32_t o = (uint32_t)(t * 64 + i * 16);
                cp16(sb + A_BUF(buf ^ 1) + o, kabase + (c + 1) * 32768 + o);
            }
            CP_COMMIT();
            // B LDG first half for chunk c+1
            bw0 = wp[0]; bw1 = wp[1]; bw2 = wp[2]; bw3 = wp[3];
        }

        // ---- ksteps 0-1: 6 ldsm + 16 mma each ----
#pragma unroll
        for (int ks = 0; ks < 2; ks++) {
            uint32_t kq = swzlt ^ ((uint32_t)ks << 5);
            uint32_t af[4][4], bh[2][4];
#pragma unroll
            for (int mt = 0; mt < 4; mt++)
                ldsm4(af[mt], Ab + (uint32_t)(mt << 11) + kq);
#pragma unroll
            for (int nt2 = 0; nt2 < 2; nt2++)
                ldsm4(bh[nt2], Bb + (uint32_t)(nt2 << 11) + kq);
#pragma unroll
            for (int mt = 0; mt < 4; mt++)
#pragma unroll
                for (int nt = 0; nt < 4; nt++)
                    mma16816h(acc[mt][nt], af[mt],
                              bh[nt >> 1][nt & 1], bh[nt >> 1][(nt & 1) + 2]);
        }

        if (c < 3) {
            // pack + STS B(c+1) first half (safe: buf^1 consumed before head sync)
#pragma unroll
            for (int k = 0; k < 2; k++) {
                float4 wA = (k == 0) ? bw0 : bw2, wB = (k == 0) ? bw1 : bw3;
                const float* q8 = qq + k * 8;
                uint4 hv;
                hv.x = packh2(wA.x * q8[0], wA.y * q8[1]);
                hv.y = packh2(wA.z * q8[2], wA.w * q8[3]);
                hv.z = packh2(wB.x * q8[4], wB.y * q8[5]);
                hv.w = packh2(wB.z * q8[6], wB.w * q8[7]);
                uint32_t o = swz((uint32_t)(bp * 128 + bq * 64 + k * 16));
                *(uint4*)(smem + B_BUF(buf ^ 1) + o) = hv;
            }
            // B LDG second half
            bw0 = wp[4]; bw1 = wp[5]; bw2 = wp[6]; bw3 = wp[7];
        }

        // ---- ksteps 2-3 ----
#pragma unroll
        for (int ks = 2; ks < 4; ks++) {
            uint32_t kq = swzlt ^ ((uint32_t)ks << 5);
            uint32_t af[4][4], bh[2][4];
#pragma unroll
            for (int mt = 0; mt < 4; mt++)
                ldsm4(af[mt], Ab + (uint32_t)(mt << 11) + kq);
#pragma unroll
            for (int nt2 = 0; nt2 < 2; nt2++)
                ldsm4(bh[nt2], Bb + (uint32_t)(nt2 << 11) + kq);
#pragma unroll
            for (int mt = 0; mt < 4; mt++)
#pragma unroll
                for (int nt = 0; nt < 4; nt++)
                    mma16816h(acc[mt][nt], af[mt],
                              bh[nt >> 1][nt & 1], bh[nt >> 1][(nt & 1) + 2]);
        }

        if (c < 3) {
            // pack + STS B(c+1) second half
#pragma unroll
            for (int k = 0; k < 2; k++) {
                float4 wA = (k == 0) ? bw0 : bw2, wB = (k == 0) ? bw1 : bw3;
                const float* q8 = qq + 16 + k * 8;
                uint4 hv;
                hv.x = packh2(wA.x * q8[0], wA.y * q8[1]);
                hv.y = packh2(wA.z * q8[2], wA.w * q8[3]);
                hv.z = packh2(wB.x * q8[4], wB.y * q8[5]);
                hv.w = packh2(wB.z * q8[6], wB.w * q8[7]);
                uint32_t o = swz((uint32_t)(bp * 128 + bq * 64 + (2 + k) * 16));
                *(uint4*)(smem + B_BUF(buf ^ 1) + o) = hv;
            }
        }
    }

    // --------------------- partial softmax epilogue ------------------------
    // acc[mt][nt][i]: local row = 64*wm + 16*mt + (lane>>2) + 8*(i>=2)
    //                 col = 32*wn + 8*nt + 2*(lane&3) + (i&1)  (within p-half)
    float* dens = (float*)(smem + OFF_DEN);   // [2 wm][128]
    float* nums = (float*)(smem + OFF_NUM);

    const float* vbase = g_v + (b << 16) + ((lh << 7) << 8) + (ph << 7);
    float dloc[4][2], nloc[4][2];
#pragma unroll
    for (int nt = 0; nt < 4; nt++) {
        dloc[nt][0] = dloc[nt][1] = 0.f;
        nloc[nt][0] = nloc[nt][1] = 0.f;
    }
#pragma unroll
    for (int mt = 0; mt < 4; mt++) {
        int row0 = 64 * wm + 16 * mt + (lane >> 2);
#pragma unroll
        for (int nt = 0; nt < 4; nt++) {
            int col = 32 * wn + 8 * nt + 2 * (lane & 3);
            float2 v0 = *(const float2*)(vbase + row0 * 256 + col);
            float2 v1 = *(const float2*)(vbase + (row0 + 8) * 256 + col);
            float e0 = __expf(acc[mt][nt][0]);
            float e1 = __expf(acc[mt][nt][1]);
            float e2 = __expf(acc[mt][nt][2]);
            float e3 = __expf(acc[mt][nt][3]);
            dloc[nt][0] += e0 + e2;
            dloc[nt][1] += e1 + e3;
            nloc[nt][0] = fmaf(e0, v0.x, fmaf(e2, v1.x, nloc[nt][0]));
            nloc[nt][1] = fmaf(e1, v0.y, fmaf(e3, v1.y, nloc[nt][1]));
        }
    }
#pragma unroll
    for (int nt = 0; nt < 4; nt++) {
#pragma unroll
        for (int d = 4; d < 32; d <<= 1) {
            dloc[nt][0] += __shfl_xor_sync(0xffffffffu, dloc[nt][0], d);
            dloc[nt][1] += __shfl_xor_sync(0xffffffffu, dloc[nt][1], d);
            nloc[nt][0] += __shfl_xor_sync(0xffffffffu, nloc[nt][0], d);
            nloc[nt][1] += __shfl_xor_sync(0xffffffffu, nloc[nt][1], d);
        }
    }
    if (lane < 4) {
#pragma unroll
        for (int nt = 0; nt < 4; nt++) {
            int col = 32 * wn + 8 * nt + 2 * lane;
            dens[wm * 128 + col]     = dloc[nt][0];
            dens[wm * 128 + col + 1] = dloc[nt][1];
            nums[wm * 128 + col]     = nloc[nt][0];
            nums[wm * 128 + col + 1] = nloc[nt][1];
        }
    }
    __syncthreads();

    if (t < 128) {
        int idx = ((b << 8) + s) * 256 + (ph << 7) + t;
        g_pden[lh * 131072 + idx] = dens[t] + dens[128 + t];
        g_pnum[lh * 131072 + idx] = nums[t] + nums[128 + t];
    }
}

// Combine the two l-half partials: out = (n0+n1)/(d0+d1). grid=512, block=256.
__global__ void combine_kernel(float* __restrict__ out) {
    int i = blockIdx.x * 256 + threadIdx.x;
    out[i] = (g_pnum[i] + g_pnum[131072 + i]) / (g_pden[i] + g_pden[131072 + i]);
}

// ---------------------------------------------------------------------------
extern "C" void kernel_launch(void* const* d_in, const int* in_sizes, int n_in,
                              void* d_out, int out_size) {
    (void)in_sizes; (void)n_in; (void)out_size;
    const float* hidden = (const float*)d_in[0];  // [2,256,256]
    const float* Wqkv   = (const float*)d_in[1];  // [768,256]
    const float* bqkv   = (const float*)d_in[2];  // [768]
    const float* Wc     = (const float*)d_in[3];  // [256,256]
    // d_in[4] = bc: constant along softmax axis -> cancels.
    float* out = (float*)d_out;

    float* pWqkvT;
    cudaGetSymbolAddress((void**)&pWqkvT, g_WqkvT);

    cudaFuncSetAttribute(attn_mma_kernel,
                         cudaFuncAttributeMaxDynamicSharedMemorySize, SMEM_BYTES);

    transpose_kernel<<<(768 / 32) * (256 / 32), 256>>>(Wqkv, pWqkvT, 768, 256);
    qkv_kernel<<<dim3(3, 64), 256>>>(hidden, bqkv);
    attn_mma_kernel<<<2048, 256, SMEM_BYTES>>>(Wc);
    combine_kernel<<<512, 256>>>(out);
}

// round 14
// speedup vs baseline: 1.2658x; 1.2658x over previous
#include <cuda_runtime.h>
#include <cuda_bf16.h>
#include <cuda_fp16.h>
#include <stdint.h>

// ---------------------------------------------------------------------------
// out[b,s,p] = sum_l softmax_l( sum_r q[b,s,r]*k[b,l,r]*Wc[p,r] ) * v[b,l,p]
// scores = K_b @ (diag(q_s) Wc^T), SINGLE-PASS fp16 mma.sync (score err RMS
// ~2e-4 << 1e-3 threshold). bc cancels; max subtraction dropped (scores O(1)).
// CTA = (b, s, ph, lh): M=128 (l-half), N=128 (p-half); grid 2048, block 256
// (8 warps 2x4, warp tile 64x32); 2 CTAs/SM. 8 chunks of 32 r, SW64 rows of
// 64B, double-buffered cp.async A; B = fp16(q*Wc) built in-kernel.
// R14 = R13 with the qkv grid coverage bug fixed (dim3(3,64): 64*8 = 512 rows).
// ---------------------------------------------------------------------------

__device__ float g_WqkvT[256 * 768];           // [h][j]
__device__ float g_q[2 * 256 * 256];
__device__ float g_v[2 * 256 * 256];
// K fp16, pre-swizzled SW64 tiles: [b][chunk 0..7][16384 bytes]
// (16KB tile = 256 l rows x 64B; row l holds 32 r values)
__device__ char g_ka[2 * 8 * 16384];
// partial softmax sums: [lh][ ((b*256+s)*256 + ph*128 + p) ]
__device__ float g_pden[2 * 131072];
__device__ float g_pnum[2 * 131072];

// ------------------------------ helpers ------------------------------------
__device__ __forceinline__ uint32_t smem_u32(const void* p) {
    uint32_t a;
    asm("{ .reg .u64 t; cvta.to.shared.u64 t, %1; cvt.u32.u64 %0, t; }"
        : "=r"(a) : "l"(p));
    return a;
}
__device__ __forceinline__ uint32_t swz64(uint32_t off) {
    return off ^ ((off >> 3) & 0x30);
}
__device__ __forceinline__ void ldsm4(uint32_t* r, uint32_t addr) {
    asm volatile("ldmatrix.sync.aligned.m8n8.x4.shared.b16 {%0,%1,%2,%3}, [%4];"
        : "=r"(r[0]), "=r"(r[1]), "=r"(r[2]), "=r"(r[3]) : "r"(addr));
}
__device__ __forceinline__ void mma16816h(float* d, const uint32_t* a,
                                          uint32_t b0, uint32_t b1) {
    asm volatile(
        "mma.sync.aligned.m16n8k16.row.col.f32.f16.f16.f32 "
        "{%0,%1,%2,%3}, {%4,%5,%6,%7}, {%8,%9}, {%0,%1,%2,%3};"
        : "+f"(d[0]), "+f"(d[1]), "+f"(d[2]), "+f"(d[3])
        : "r"(a[0]), "r"(a[1]), "r"(a[2]), "r"(a[3]), "r"(b0), "r"(b1));
}
// pack two fp32 -> fp16x2 (v0 in low half)
__device__ __forceinline__ uint32_t packh2(float v0, float v1) {
    uint32_t h;
    asm("cvt.rn.f16x2.f32 %0, %1, %2;" : "=r"(h) : "f"(v1), "f"(v0));
    return h;
}
__device__ __forceinline__ void cp16(uint32_t dst, const void* src) {
    asm volatile("cp.async.cg.shared.global [%0], [%1], 16;"
                 :: "r"(dst), "l"(src));
}
#define CP_COMMIT() asm volatile("cp.async.commit_group;" ::: "memory")
#define CP_WAIT0()  asm volatile("cp.async.wait_group 0;" ::: "memory")

// ---------------------------------------------------------------------------
// Prep kernels
// ---------------------------------------------------------------------------
__global__ void transpose_kernel(const float* __restrict__ in, float* __restrict__ out,
                                 int rows, int cols) {
    __shared__ float tile[32][33];
    int ctiles = cols >> 5;
    int bx = blockIdx.x % ctiles, by = blockIdx.x / ctiles;
    int c0 = bx << 5, r0 = by << 5;
    int tx = threadIdx.x & 31, ty = threadIdx.x >> 5;
#pragma unroll
    for (int i = ty; i < 32; i += 8)
        tile[i][tx] = in[(r0 + i) * cols + c0 + tx];
    __syncthreads();
#pragma unroll
    for (int i = ty; i < 32; i += 8)
        out[(c0 + i) * rows + r0 + tx] = tile[tx][i];
}

// QKV projection, 2D grid: blockIdx.x = j-block (0:q 1:k 2:v), blockIdx.y =
// row-block (8 rows each; 64 blocks cover all 512 rows). block = 256.
// K section writes fp16 directly into the pre-swizzled SW64 g_ka tiles.
__global__ void qkv_kernel(const float* __restrict__ hidden,
                           const float* __restrict__ bqkv) {
    __shared__ float hs[8][256];
    int t = threadIdx.x;
    int jb = blockIdx.x;
    int row0 = blockIdx.y << 3;
    for (int i = t; i < 2048; i += 256)
        hs[i >> 8][i & 255] = hidden[(row0 << 8) + i];
    __syncthreads();

    int j = jb * 256 + t;
    float a[8];
#pragma unroll
    for (int i = 0; i < 8; i++) a[i] = 0.f;
    const float* w = g_WqkvT + j;
#pragma unroll 8
    for (int h = 0; h < 256; h++) {
        float wv = w[h * 768];
#pragma unroll
        for (int i = 0; i < 8; i++) a[i] = fmaf(hs[i][h], wv, a[i]);
    }
    float bias = bqkv[j];
#pragma unroll
    for (int i = 0; i < 8; i++) a[i] += bias;

    if (jb == 1) {
        // K: fp16 into pre-swizzled SW64 tiles. r = t.
        int c = t >> 5, rl = t & 31;
#pragma unroll
        for (int i = 0; i < 8; i++) {
            int row = row0 + i;
            int b = row >> 8, l = row & 255;
            uint32_t off = swz64((uint32_t)(l * 64 + rl * 2));
            char* base = g_ka + ((b * 8 + c) << 14);
            *(unsigned short*)(base + off) =
                __half_as_ushort(__float2half_rn(a[i]));
        }
    } else {
        float* dst = (jb == 0) ? g_q : g_v;
#pragma unroll
        for (int i = 0; i < 8; i++)
            dst[(row0 + i) * 256 + t] = a[i];
    }
}

// ---------------------------------------------------------------------------
// Fused attention kernel. CTA = (b, s, ph, lh). grid = 2048, block = 256.
// 8 warps as 2(M) x 4(N), warp tile 64x32. 8 chunks of 32 r, double buffered.
// ---------------------------------------------------------------------------
#define A_BUF(buf) ((uint32_t)(buf) * 8192u)
#define B_BUF(buf) (16384u + (uint32_t)(buf) * 8192u)
#define OFF_QS  32768
#define OFF_DEN 33792
#define OFF_NUM 34816
#define SMEM_BYTES 35840

__global__ void __launch_bounds__(256, 2)
attn_mma_kernel(const float* __restrict__ Wc) {
    extern __shared__ char smem[];
    uint32_t sb = smem_u32(smem);
    int t = threadIdx.x;
    int lane = t & 31, w = t >> 5;
    int wm = w & 1, wn = w >> 1;           // 2(M) x 4(N) warps; tile 64 x 32
    int lh = blockIdx.x & 1;
    int ph = (blockIdx.x >> 1) & 1;
    int s = (blockIdx.x >> 2) & 255;
    int b = blockIdx.x >> 10;

    float* qs = (float*)(smem + OFF_QS);

    float acc[4][4][4];
#pragma unroll
    for (int mt = 0; mt < 4; mt++)
#pragma unroll
        for (int nt = 0; nt < 4; nt++)
#pragma unroll
            for (int i = 0; i < 4; i++) acc[mt][nt][i] = 0.f;

    // ldmatrix lane byte offset for 64B rows; hoisted SW64 swizzle (XOR form).
    int g = lane >> 3;
    uint32_t laneterm = (uint32_t)((((g & 1) << 3) + (lane & 7)) * 64 + ((g >> 1) << 4));
    uint32_t swzlt = swz64(laneterm);
    uint32_t arowoff = (uint32_t)(wm * 64) * 64;   // 4096*wm
    uint32_t browoff = (uint32_t)(wn * 32) * 64;   // 2048*wn

    // B staging: thread -> (p row bp, 16-r half bq)
    int bp = t >> 1, bq = t & 1;
    const float* wcrow = Wc + ((ph << 7) + bp) * 256;
    const char* kabase = g_ka + ((b * 8) << 14) + lh * 8192;  // + c*16384

    // ---- prologue: cp.async A chunk0, q load, B chunk0 ----
#pragma unroll
    for (int i = 0; i < 2; i++) {
        uint32_t o = (uint32_t)(t * 32 + i * 16);
        cp16(sb + A_BUF(0) + o, kabase + o);
    }
    CP_COMMIT();
    qs[t] = g_q[((b << 8) + s) * 256 + t];
    __syncthreads();
    {
        const float4* wp = (const float4*)(wcrow + bq * 16);
        float4 bw0 = wp[0], bw1 = wp[1], bw2 = wp[2], bw3 = wp[3];
        const float* qq = qs + bq * 16;
        uint4 hv0, hv1;
        hv0.x = packh2(bw0.x * qq[0],  bw0.y * qq[1]);
        hv0.y = packh2(bw0.z * qq[2],  bw0.w * qq[3]);
        hv0.z = packh2(bw1.x * qq[4],  bw1.y * qq[5]);
        hv0.w = packh2(bw1.z * qq[6],  bw1.w * qq[7]);
        hv1.x = packh2(bw2.x * qq[8],  bw2.y * qq[9]);
        hv1.y = packh2(bw2.z * qq[10], bw2.w * qq[11]);
        hv1.z = packh2(bw3.x * qq[12], bw3.y * qq[13]);
        hv1.w = packh2(bw3.z * qq[14], bw3.w * qq[15]);
        uint32_t o0 = swz64((uint32_t)(bp * 64 + bq * 32));
        uint32_t o1 = swz64((uint32_t)(bp * 64 + bq * 32 + 16));
        *(uint4*)(smem + B_BUF(0) + o0) = hv0;
        *(uint4*)(smem + B_BUF(0) + o1) = hv1;
    }

    // ---- main loop over 8 chunks of 32 r ----
    for (int c = 0; c < 8; c++) {
        int buf = c & 1;
        CP_WAIT0();
        __syncthreads();

        float4 bw0, bw1, bw2, bw3;
        if (c < 7) {
#pragma unroll
            for (int i = 0; i < 2; i++) {
                uint32_t o = (uint32_t)(t * 32 + i * 16);
                cp16(sb + A_BUF(buf ^ 1) + o, kabase + (c + 1) * 16384 + o);
            }
            CP_COMMIT();
            const float4* wp = (const float4*)(wcrow + (c + 1) * 32 + bq * 16);
            bw0 = wp[0]; bw1 = wp[1]; bw2 = wp[2]; bw3 = wp[3];
        }

        // ---- single-pass fp16 mma: 2 ksteps x (6 ldsm + 16 mma) ----
        {
            uint32_t Ab = sb + A_BUF(buf) + arowoff;
            uint32_t Bb = sb + B_BUF(buf) + browoff;
#pragma unroll
            for (int ks = 0; ks < 2; ks++) {
                uint32_t kq = swzlt ^ ((uint32_t)ks << 5);
                uint32_t af[4][4], bh[2][4];
#pragma unroll
                for (int mt = 0; mt < 4; mt++)
                    ldsm4(af[mt], Ab + (uint32_t)(mt << 10) + kq);
#pragma unroll
                for (int nt2 = 0; nt2 < 2; nt2++)
                    ldsm4(bh[nt2], Bb + (uint32_t)(nt2 << 10) + kq);
#pragma unroll
                for (int mt = 0; mt < 4; mt++)
#pragma unroll
                    for (int nt = 0; nt < 4; nt++)
                        mma16816h(acc[mt][nt], af[mt],
                                  bh[nt >> 1][nt & 1], bh[nt >> 1][(nt & 1) + 2]);
            }
        }

        if (c < 7) {
            const float* qq = qs + (c + 1) * 32 + bq * 16;
            uint4 hv0, hv1;
            hv0.x = packh2(bw0.x * qq[0],  bw0.y * qq[1]);
            hv0.y = packh2(bw0.z * qq[2],  bw0.w * qq[3]);
            hv0.z = packh2(bw1.x * qq[4],  bw1.y * qq[5]);
            hv0.w = packh2(bw1.z * qq[6],  bw1.w * qq[7]);
            hv1.x = packh2(bw2.x * qq[8],  bw2.y * qq[9]);
            hv1.y = packh2(bw2.z * qq[10], bw2.w * qq[11]);
            hv1.z = packh2(bw3.x * qq[12], bw3.y * qq[13]);
            hv1.w = packh2(bw3.z * qq[14], bw3.w * qq[15]);
            uint32_t o0 = swz64((uint32_t)(bp * 64 + bq * 32));
            uint32_t o1 = swz64((uint32_t)(bp * 64 + bq * 32 + 16));
            *(uint4*)(smem + B_BUF(buf ^ 1) + o0) = hv0;
            *(uint4*)(smem + B_BUF(buf ^ 1) + o1) = hv1;
        }
    }

    // --------------------- partial softmax epilogue ------------------------
    // acc[mt][nt][i]: local row = 64*wm + 16*mt + (lane>>2) + 8*(i>=2)
    //                 col = 32*wn + 8*nt + 2*(lane&3) + (i&1)  (within p-half)
    float* dens = (float*)(smem + OFF_DEN);   // [2 wm][128]
    float* nums = (float*)(smem + OFF_NUM);

    const float* vbase = g_v + (b << 16) + ((lh << 7) << 8) + (ph << 7);
    float dloc[4][2], nloc[4][2];
#pragma unroll
    for (int nt = 0; nt < 4; nt++) {
        dloc[nt][0] = dloc[nt][1] = 0.f;
        nloc[nt][0] = nloc[nt][1] = 0.f;
    }
#pragma unroll
    for (int mt = 0; mt < 4; mt++) {
        int row0 = 64 * wm + 16 * mt + (lane >> 2);
#pragma unroll
        for (int nt = 0; nt < 4; nt++) {
            int col = 32 * wn + 8 * nt + 2 * (lane & 3);
            float2 v0 = *(const float2*)(vbase + row0 * 256 + col);
            float2 v1 = *(const float2*)(vbase + (row0 + 8) * 256 + col);
            float e0 = __expf(acc[mt][nt][0]);
            float e1 = __expf(acc[mt][nt][1]);
            float e2 = __expf(acc[mt][nt][2]);
            float e3 = __expf(acc[mt][nt][3]);
            dloc[nt][0] += e0 + e2;
            dloc[nt][1] += e1 + e3;
            nloc[nt][0] = fmaf(e0, v0.x, fmaf(e2, v1.x, nloc[nt][0]));
            nloc[nt][1] = fmaf(e1, v0.y, fmaf(e3, v1.y, nloc[nt][1]));
        }
    }
#pragma unroll
    for (int nt = 0; nt < 4; nt++) {
#pragma unroll
        for (int d = 4; d < 32; d <<= 1) {
            dloc[nt][0] += __shfl_xor_sync(0xffffffffu, dloc[nt][0], d);
            dloc[nt][1] += __shfl_xor_sync(0xffffffffu, dloc[nt][1], d);
            nloc[nt][0] += __shfl_xor_sync(0xffffffffu, nloc[nt][0], d);
            nloc[nt][1] += __shfl_xor_sync(0xffffffffu, nloc[nt][1], d);
        }
    }
    if (lane < 4) {
#pragma unroll
        for (int nt = 0; nt < 4; nt++) {
            int col = 32 * wn + 8 * nt + 2 * lane;
            dens[wm * 128 + col]     = dloc[nt][0];
            dens[wm * 128 + col + 1] = dloc[nt][1];
            nums[wm * 128 + col]     = nloc[nt][0];
            nums[wm * 128 + col + 1] = nloc[nt][1];
        }
    }
    __syncthreads();

    if (t < 128) {
        int idx = ((b << 8) + s) * 256 + (ph << 7) + t;
        g_pden[lh * 131072 + idx] = dens[t] + dens[128 + t];
        g_pnum[lh * 131072 + idx] = nums[t] + nums[128 + t];
    }
}

// Combine the two l-half partials: out = (n0+n1)/(d0+d1). grid=512, block=256.
__global__ void combine_kernel(float* __restrict__ out) {
    int i = blockIdx.x * 256 + threadIdx.x;
    out[i] = (g_pnum[i] + g_pnum[131072 + i]) / (g_pden[i] + g_pden[131072 + i]);
}

// ---------------------------------------------------------------------------
extern "C" void kernel_launch(void* const* d_in, const int* in_sizes, int n_in,
                              void* d_out, int out_size) {
    (void)in_sizes; (void)n_in; (void)out_size;
    const float* hidden = (const float*)d_in[0];  // [2,256,256]
    const float* Wqkv   = (const float*)d_in[1];  // [768,256]
    const float* bqkv   = (const float*)d_in[2];  // [768]
    const float* Wc     = (const float*)d_in[3];  // [256,256]
    // d_in[4] = bc: constant along softmax axis -> cancels.
    float* out = (float*)d_out;

    float* pWqkvT;
    cudaGetSymbolAddress((void**)&pWqkvT, g_WqkvT);

    cudaFuncSetAttribute(attn_mma_kernel,
                         cudaFuncAttributeMaxDynamicSharedMemorySize, SMEM_BYTES);

    transpose_kernel<<<(768 / 32) * (256 / 32), 256>>>(Wqkv, pWqkvT, 768, 256);
    qkv_kernel<<<dim3(3, 64), 256>>>(hidden, bqkv);    // 64*8 = 512 rows
    attn_mma_kernel<<<2048, 256, SMEM_BYTES>>>(Wc);
    combine_kernel<<<512, 256>>>(out);
}

// round 15
// speedup vs baseline: 1.4685x; 1.1602x over previous
#include <cuda_runtime.h>
#include <cuda_bf16.h>
#include <cuda_fp16.h>
#include <stdint.h>

// ---------------------------------------------------------------------------
// out[b,s,p] = sum_l softmax_l( sum_r q[b,s,r]*k[b,l,r]*Wc[p,r] ) * v[b,l,p]
// scores = K_b @ (diag(q_s) Wc^T), SINGLE-PASS fp16 mma.sync. bc cancels;
// max subtraction dropped (scores O(1)). CTA = (b, s, ph, lh); grid 2048,
// block 256 (8 warps 2x4, warp tile 64x32); 2 CTAs/SM. 8 chunks of 32 r,
// SW64 64B rows, double-buffered cp.async A.
// R15: B = HMUL2(fp16(q), fp16(Wc)) — kills the fp32 mul+cvt B-build that
// audit showed was ~95us of SMSP issue (3x fewer staging instructions).
// ---------------------------------------------------------------------------

__device__ float g_WqkvT[256 * 768];           // [h][j]
__device__ float g_q[2 * 256 * 256];
__device__ float g_v[2 * 256 * 256];
__device__ unsigned short g_wch[256 * 256];    // Wc as fp16, [p][r]
// K fp16, pre-swizzled SW64 tiles: [b][chunk 0..7][16384 bytes]
__device__ char g_ka[2 * 8 * 16384];
// partial softmax sums: [lh][ ((b*256+s)*256 + ph*128 + p) ]
__device__ float g_pden[2 * 131072];
__device__ float g_pnum[2 * 131072];

// ------------------------------ helpers ------------------------------------
__device__ __forceinline__ uint32_t smem_u32(const void* p) {
    uint32_t a;
    asm("{ .reg .u64 t; cvta.to.shared.u64 t, %1; cvt.u32.u64 %0, t; }"
        : "=r"(a) : "l"(p));
    return a;
}
__device__ __forceinline__ uint32_t swz64(uint32_t off) {
    return off ^ ((off >> 3) & 0x30);
}
__device__ __forceinline__ void ldsm4(uint32_t* r, uint32_t addr) {
    asm volatile("ldmatrix.sync.aligned.m8n8.x4.shared.b16 {%0,%1,%2,%3}, [%4];"
        : "=r"(r[0]), "=r"(r[1]), "=r"(r[2]), "=r"(r[3]) : "r"(addr));
}
__device__ __forceinline__ void mma16816h(float* d, const uint32_t* a,
                                          uint32_t b0, uint32_t b1) {
    asm volatile(
        "mma.sync.aligned.m16n8k16.row.col.f32.f16.f16.f32 "
        "{%0,%1,%2,%3}, {%4,%5,%6,%7}, {%8,%9}, {%0,%1,%2,%3};"
        : "+f"(d[0]), "+f"(d[1]), "+f"(d[2]), "+f"(d[3])
        : "r"(a[0]), "r"(a[1]), "r"(a[2]), "r"(a[3]), "r"(b0), "r"(b1));
}
// pack two fp32 -> fp16x2 (v0 in low half)
__device__ __forceinline__ uint32_t packh2(float v0, float v1) {
    uint32_t h;
    asm("cvt.rn.f16x2.f32 %0, %1, %2;" : "=r"(h) : "f"(v1), "f"(v0));
    return h;
}
__device__ __forceinline__ uint32_t hmul2(uint32_t a, uint32_t b) {
    uint32_t r;
    asm("mul.rn.f16x2 %0, %1, %2;" : "=r"(r) : "r"(a), "r"(b));
    return r;
}
__device__ __forceinline__ void cp16(uint32_t dst, const void* src) {
    asm volatile("cp.async.cg.shared.global [%0], [%1], 16;"
                 :: "r"(dst), "l"(src));
}
#define CP_COMMIT() asm volatile("cp.async.commit_group;" ::: "memory")
#define CP_WAIT0()  asm volatile("cp.async.wait_group 0;" ::: "memory")

// ---------------------------------------------------------------------------
// Prep kernels
// ---------------------------------------------------------------------------
__global__ void transpose_kernel(const float* __restrict__ in, float* __restrict__ out,
                                 int rows, int cols) {
    __shared__ float tile[32][33];
    int ctiles = cols >> 5;
    int bx = blockIdx.x % ctiles, by = blockIdx.x / ctiles;
    int c0 = bx << 5, r0 = by << 5;
    int tx = threadIdx.x & 31, ty = threadIdx.x >> 5;
#pragma unroll
    for (int i = ty; i < 32; i += 8)
        tile[i][tx] = in[(r0 + i) * cols + c0 + tx];
    __syncthreads();
#pragma unroll
    for (int i = ty; i < 32; i += 8)
        out[(c0 + i) * rows + r0 + tx] = tile[tx][i];
}

// Convert Wc (fp32 [p][r]) to fp16x2 words. grid=32, block=256, 4 words/thread.
__global__ void wcprep_kernel(const float* __restrict__ Wc) {
    int gt = blockIdx.x * 256 + threadIdx.x;
    const float2* src = (const float2*)Wc;
    uint32_t* dst = (uint32_t*)g_wch;
#pragma unroll
    for (int k = 0; k < 4; k++) {
        int i = gt * 4 + k;
        float2 f = src[i];
        dst[i] = packh2(f.x, f.y);
    }
}

// QKV projection (R11 1D version); K section writes fp16 directly into the
// pre-swizzled SW64 g_ka tiles. grid=128, block=768.
__global__ void qkv_kernel(const float* __restrict__ hidden,
                           const float* __restrict__ bqkv) {
    __shared__ float hs[4][256];
    int t = threadIdx.x;
    int row0 = blockIdx.x << 2;
    for (int i = t; i < 1024; i += 768)
        hs[i >> 8][i & 255] = hidden[(row0 << 8) + i];
    __syncthreads();
    float a0 = 0.f, a1 = 0.f, a2 = 0.f, a3 = 0.f;
    const float* w = g_WqkvT + t;
#pragma unroll 8
    for (int h = 0; h < 256; h++) {
        float wv = w[h * 768];
        a0 = fmaf(hs[0][h], wv, a0);
        a1 = fmaf(hs[1][h], wv, a1);
        a2 = fmaf(hs[2][h], wv, a2);
        a3 = fmaf(hs[3][h], wv, a3);
    }
    float bias = bqkv[t];
    a0 += bias; a1 += bias; a2 += bias; a3 += bias;
    int sect = t >> 8, j = t & 255;
    if (sect == 1) {
        // K: fp16 into pre-swizzled SW64 tiles. r = j.
        int c = j >> 5, rl = j & 31;
        float av[4] = {a0, a1, a2, a3};
#pragma unroll
        for (int i = 0; i < 4; i++) {
            int row = row0 + i;
            int b = row >> 8, l = row & 255;
            uint32_t off = swz64((uint32_t)(l * 64 + rl * 2));
            char* base = g_ka + ((b * 8 + c) << 14);
            *(unsigned short*)(base + off) =
                __half_as_ushort(__float2half_rn(av[i]));
        }
    } else {
        float* dst = (sect == 0) ? g_q : g_v;
        dst[(row0 + 0) * 256 + j] = a0;
        dst[(row0 + 1) * 256 + j] = a1;
        dst[(row0 + 2) * 256 + j] = a2;
        dst[(row0 + 3) * 256 + j] = a3;
    }
}

// ---------------------------------------------------------------------------
// Fused attention kernel. CTA = (b, s, ph, lh). grid = 2048, block = 256.
// 8 warps as 2(M) x 4(N), warp tile 64x32. 8 chunks of 32 r, double buffered.
// ---------------------------------------------------------------------------
#define A_BUF(buf) ((uint32_t)(buf) * 8192u)
#define B_BUF(buf) (16384u + (uint32_t)(buf) * 8192u)
#define OFF_QS  32768
#define OFF_DEN 33792
#define OFF_NUM 34816
#define SMEM_BYTES 35840

__global__ void __launch_bounds__(256, 2)
attn_mma_kernel(void) {
    extern __shared__ char smem[];
    uint32_t sb = smem_u32(smem);
    int t = threadIdx.x;
    int lane = t & 31, w = t >> 5;
    int wm = w & 1, wn = w >> 1;           // 2(M) x 4(N) warps; tile 64 x 32
    int lh = blockIdx.x & 1;
    int ph = (blockIdx.x >> 1) & 1;
    int s = (blockIdx.x >> 2) & 255;
    int b = blockIdx.x >> 10;

    uint32_t* qh2 = (uint32_t*)(smem + OFF_QS);   // 128 fp16x2 words of q

    float acc[4][4][4];
#pragma unroll
    for (int mt = 0; mt < 4; mt++)
#pragma unroll
        for (int nt = 0; nt < 4; nt++)
#pragma unroll
            for (int i = 0; i < 4; i++) acc[mt][nt][i] = 0.f;

    // ldmatrix lane byte offset for 64B rows; hoisted SW64 swizzle (XOR form).
    int g = lane >> 3;
    uint32_t laneterm = (uint32_t)((((g & 1) << 3) + (lane & 7)) * 64 + ((g >> 1) << 4));
    uint32_t swzlt = swz64(laneterm);
    uint32_t arowoff = (uint32_t)(wm * 64) * 64;   // 4096*wm
    uint32_t browoff = (uint32_t)(wn * 32) * 64;   // 2048*wn

    // B staging: thread -> (p row bp, 16-r half bq)
    int bp = t >> 1, bq = t & 1;
    const unsigned short* wchrow = g_wch + ((ph << 7) + bp) * 256 + bq * 16;
    const char* kabase = g_ka + ((b * 8) << 14) + lh * 8192;  // + c*16384

    // ---- prologue: cp.async A chunk0, q load+convert, B chunk0 ----
#pragma unroll
    for (int i = 0; i < 2; i++) {
        uint32_t o = (uint32_t)(t * 32 + i * 16);
        cp16(sb + A_BUF(0) + o, kabase + o);
    }
    CP_COMMIT();
    if (t < 128) {
        float2 qf = ((const float2*)(g_q + ((b << 8) + s) * 256))[t];
        qh2[t] = packh2(qf.x, qf.y);
    }
    __syncthreads();
    {
        const uint4* wp = (const uint4*)wchrow;          // chunk 0
        uint4 wa = wp[0], wb = wp[1];
        const uint4* qp = (const uint4*)(qh2 + bq * 8);
        uint4 qa = qp[0], qb = qp[1];
        uint4 hv0, hv1;
        hv0.x = hmul2(wa.x, qa.x); hv0.y = hmul2(wa.y, qa.y);
        hv0.z = hmul2(wa.z, qa.z); hv0.w = hmul2(wa.w, qa.w);
        hv1.x = hmul2(wb.x, qb.x); hv1.y = hmul2(wb.y, qb.y);
        hv1.z = hmul2(wb.z, qb.z); hv1.w = hmul2(wb.w, qb.w);
        uint32_t o0 = swz64((uint32_t)(bp * 64 + bq * 32));
        uint32_t o1 = swz64((uint32_t)(bp * 64 + bq * 32 + 16));
        *(uint4*)(smem + B_BUF(0) + o0) = hv0;
        *(uint4*)(smem + B_BUF(0) + o1) = hv1;
    }

    // ---- main loop over 8 chunks of 32 r ----
    for (int c = 0; c < 8; c++) {
        int buf = c & 1;
        CP_WAIT0();
        __syncthreads();

        uint4 wa, wb;
        if (c < 7) {
#pragma unroll
            for (int i = 0; i < 2; i++) {
                uint32_t o = (uint32_t)(t * 32 + i * 16);
                cp16(sb + A_BUF(buf ^ 1) + o, kabase + (c + 1) * 16384 + o);
            }
            CP_COMMIT();
            // Wc fp16 LDG for chunk c+1 (latency hidden under mma)
            const uint4* wp = (const uint4*)(wchrow + (c + 1) * 32);
            wa = wp[0]; wb = wp[1];
        }

        // ---- single-pass fp16 mma: 2 ksteps x (6 ldsm + 16 mma) ----
        {
            uint32_t Ab = sb + A_BUF(buf) + arowoff;
            uint32_t Bb = sb + B_BUF(buf) + browoff;
#pragma unroll
            for (int ks = 0; ks < 2; ks++) {
                uint32_t kq = swzlt ^ ((uint32_t)ks << 5);
                uint32_t af[4][4], bh[2][4];
#pragma unroll
                for (int mt = 0; mt < 4; mt++)
                    ldsm4(af[mt], Ab + (uint32_t)(mt << 10) + kq);
#pragma unroll
                for (int nt2 = 0; nt2 < 2; nt2++)
                    ldsm4(bh[nt2], Bb + (uint32_t)(nt2 << 10) + kq);
#pragma unroll
                for (int mt = 0; mt < 4; mt++)
#pragma unroll
                    for (int nt = 0; nt < 4; nt++)
                        mma16816h(acc[mt][nt], af[mt],
                                  bh[nt >> 1][nt & 1], bh[nt >> 1][(nt & 1) + 2]);
            }
        }

        if (c < 7) {
            const uint4* qp = (const uint4*)(qh2 + (c + 1) * 16 + bq * 8);
            uint4 qa = qp[0], qb = qp[1];
            uint4 hv0, hv1;
            hv0.x = hmul2(wa.x, qa.x); hv0.y = hmul2(wa.y, qa.y);
            hv0.z = hmul2(wa.z, qa.z); hv0.w = hmul2(wa.w, qa.w);
            hv1.x = hmul2(wb.x, qb.x); hv1.y = hmul2(wb.y, qb.y);
            hv1.z = hmul2(wb.z, qb.z); hv1.w = hmul2(wb.w, qb.w);
            uint32_t o0 = swz64((uint32_t)(bp * 64 + bq * 32));
            uint32_t o1 = swz64((uint32_t)(bp * 64 + bq * 32 + 16));
            *(uint4*)(smem + B_BUF(buf ^ 1) + o0) = hv0;
            *(uint4*)(smem + B_BUF(buf ^ 1) + o1) = hv1;
        }
    }

    // --------------------- partial softmax epilogue ------------------------
    // acc[mt][nt][i]: local row = 64*wm + 16*mt + (lane>>2) + 8*(i>=2)
    //                 col = 32*wn + 8*nt + 2*(lane&3) + (i&1)  (within p-half)
    float* dens = (float*)(smem + OFF_DEN);   // [2 wm][128]
    float* nums = (float*)(smem + OFF_NUM);

    const float* vbase = g_v + (b << 16) + ((lh << 7) << 8) + (ph << 7);
    float dloc[4][2], nloc[4][2];
#pragma unroll
    for (int nt = 0; nt < 4; nt++) {
        dloc[nt][0] = dloc[nt][1] = 0.f;
        nloc[nt][0] = nloc[nt][1] = 0.f;
    }
#pragma unroll
    for (int mt = 0; mt < 4; mt++) {
        int row0 = 64 * wm + 16 * mt + (lane >> 2);
#pragma unroll
        for (int nt = 0; nt < 4; nt++) {
            int col = 32 * wn + 8 * nt + 2 * (lane & 3);
            float2 v0 = *(const float2*)(vbase + row0 * 256 + col);
            float2 v1 = *(const float2*)(vbase + (row0 + 8) * 256 + col);
            float e0 = __expf(acc[mt][nt][0]);
            float e1 = __expf(acc[mt][nt][1]);
            float e2 = __expf(acc[mt][nt][2]);
            float e3 = __expf(acc[mt][nt][3]);
            dloc[nt][0] += e0 + e2;
            dloc[nt][1] += e1 + e3;
            nloc[nt][0] = fmaf(e0, v0.x, fmaf(e2, v1.x, nloc[nt][0]));
            nloc[nt][1] = fmaf(e1, v0.y, fmaf(e3, v1.y, nloc[nt][1]));
        }
    }
#pragma unroll
    for (int nt = 0; nt < 4; nt++) {
#pragma unroll
        for (int d = 4; d < 32; d <<= 1) {
            dloc[nt][0] += __shfl_xor_sync(0xffffffffu, dloc[nt][0], d);
            dloc[nt][1] += __shfl_xor_sync(0xffffffffu, dloc[nt][1], d);
            nloc[nt][0] += __shfl_xor_sync(0xffffffffu, nloc[nt][0], d);
            nloc[nt][1] += __shfl_xor_sync(0xffffffffu, nloc[nt][1], d);
        }
    }
    if (lane < 4) {
#pragma unroll
        for (int nt = 0; nt < 4; nt++) {
            int col = 32 * wn + 8 * nt + 2 * lane;
            dens[wm * 128 + col]     = dloc[nt][0];
            dens[wm * 128 + col + 1] = dloc[nt][1];
            nums[wm * 128 + col]     = nloc[nt][0];
            nums[wm * 128 + col + 1] = nloc[nt][1];
        }
    }
    __syncthreads();

    if (t < 128) {
        int idx = ((b << 8) + s) * 256 + (ph << 7) + t;
        g_pden[lh * 131072 + idx] = dens[t] + dens[128 + t];
        g_pnum[lh * 131072 + idx] = nums[t] + nums[128 + t];
    }
}

// Combine the two l-half partials: out = (n0+n1)/(d0+d1). grid=512, block=256.
__global__ void combine_kernel(float* __restrict__ out) {
    int i = blockIdx.x * 256 + threadIdx.x;
    out[i] = (g_pnum[i] + g_pnum[131072 + i]) / (g_pden[i] + g_pden[131072 + i]);
}

// ---------------------------------------------------------------------------
extern "C" void kernel_launch(void* const* d_in, const int* in_sizes, int n_in,
                              void* d_out, int out_size) {
    (void)in_sizes; (void)n_in; (void)out_size;
    const float* hidden = (const float*)d_in[0];  // [2,256,256]
    const float* Wqkv   = (const float*)d_in[1];  // [768,256]
    const float* bqkv   = (const float*)d_in[2];  // [768]
    const float* Wc     = (const float*)d_in[3];  // [256,256]
    // d_in[4] = bc: constant along softmax axis -> cancels.
    float* out = (float*)d_out;

    float* pWqkvT;
    cudaGetSymbolAddress((void**)&pWqkvT, g_WqkvT);

    cudaFuncSetAttribute(attn_mma_kernel,
                         cudaFuncAttributeMaxDynamicSharedMemorySize, SMEM_BYTES);

    transpose_kernel<<<(768 / 32) * (256 / 32), 256>>>(Wqkv, pWqkvT, 768, 256);
    wcprep_kernel<<<32, 256>>>(Wc);
    qkv_kernel<<<128, 768>>>(hidden, bqkv);
    attn_mma_kernel<<<2048, 256, SMEM_BYTES>>>();
    combine_kernel<<<512, 256>>>(out);
}